// round 3
// baseline (speedup 1.0000x reference)
#include <cuda_runtime.h>
#include <cstdint>

#define BATCH   8192
#define DINA    4096
#define DINB    2048
#define DLAT    256
#define NCODE   8192
#define BETA_F  0.25f

// ---------------- scratch (static __device__ — no allocation) ----------------
__device__ float g_ze_a0[BATCH * DLAT];
__device__ float g_ze_a1[BATCH * DLAT];
__device__ float g_ze_b0[BATCH * DLAT];
__device__ float g_ze_b1[BATCH * DLAT];
__device__ float g_h0[2 * BATCH * DLAT];
__device__ float g_h1[2 * BATCH * DLAT];
__device__ double g_zz_a[BATCH];
__device__ double g_zz_b[BATCH];
__device__ unsigned long long g_amin_a[BATCH];
__device__ unsigned long long g_amin_b[BATCH];

// ---------------- small helpers ----------------
__global__ void init_amin_kernel() {
    int i = blockIdx.x * blockDim.x + threadIdx.x;
    if (i < BATCH) { g_amin_a[i] = ~0ull; g_amin_b[i] = ~0ull; }
}

// ||z_row||^2 in fp64 (only the binade + approx value are consumed)
__global__ void zz_kernel(const float* __restrict__ Z, double* __restrict__ zz) {
    int row  = blockIdx.x * 8 + (threadIdx.x >> 5);
    int lane = threadIdx.x & 31;
    const float4* zp = reinterpret_cast<const float4*>(Z) + (size_t)row * (DLAT / 4);
    double s = 0.0;
#pragma unroll
    for (int t = 0; t < 2; t++) {
        float4 v = zp[lane + 32 * t];
        s += (double)v.x * v.x + (double)v.y * v.y
           + (double)v.z * v.z + (double)v.w * v.w;
    }
#pragma unroll
    for (int o = 16; o; o >>= 1) s += __shfl_down_sync(0xffffffffu, s, o);
    if (lane == 0) zz[row] = s;
}

// ---------------- generic fused GEMM ----------------
// C = [RESID? A +] [RELU?] (A @ W + bias)
// fp32 sequential ascending-k FMA accumulation (cublas-sgemm-like rounding).
template<bool RELU, bool RESID>
__global__ __launch_bounds__(256)
void gemm_kernel(const float* __restrict__ A, const float* __restrict__ W,
                 const float* __restrict__ bias,
                 float* __restrict__ C0, float* __restrict__ C1, int rowSplit,
                 int M, int N, int K)
{
    __shared__ float As[16][128];
    __shared__ float Bs[16][64];
    const int tid = threadIdx.x;
    const int tx = tid & 15, ty = tid >> 4;
    const int rowBase = blockIdx.y * 128;
    const int colBase = blockIdx.x * 64;

    float acc[8][4];
#pragma unroll
    for (int i = 0; i < 8; i++)
#pragma unroll
        for (int j = 0; j < 4; j++) acc[i][j] = 0.f;

    const int br0 = tid >> 4, bc0 = tid & 15;

    for (int k0 = 0; k0 < K; k0 += 16) {
#pragma unroll
        for (int s = 0; s < 2; s++) {
            int f = tid + s * 256;
            int r = f >> 2, c4 = f & 3;
            float4 v = *(reinterpret_cast<const float4*>(
                           A + (size_t)(rowBase + r) * K + k0) + c4);
            As[c4 * 4 + 0][r] = v.x; As[c4 * 4 + 1][r] = v.y;
            As[c4 * 4 + 2][r] = v.z; As[c4 * 4 + 3][r] = v.w;
        }
        {
            float4 v = *(reinterpret_cast<const float4*>(
                           W + (size_t)(k0 + br0) * N + colBase) + bc0);
            *reinterpret_cast<float4*>(&Bs[br0][bc0 * 4]) = v;
        }
        __syncthreads();
#pragma unroll
        for (int kk = 0; kk < 16; kk++) {
            float ra[8], rb[4];
#pragma unroll
            for (int i = 0; i < 8; i++) ra[i] = As[kk][ty + 16 * i];
#pragma unroll
            for (int j = 0; j < 4; j++) rb[j] = Bs[kk][tx + 16 * j];
#pragma unroll
            for (int i = 0; i < 8; i++)
#pragma unroll
                for (int j = 0; j < 4; j++)
                    acc[i][j] = fmaf(ra[i], rb[j], acc[i][j]);
        }
        __syncthreads();
    }

#pragma unroll
    for (int i = 0; i < 8; i++) {
        int row = rowBase + ty + 16 * i;
        float* cr = (row < rowSplit) ? (C0 + (size_t)row * N)
                                     : (C1 + (size_t)(row - rowSplit) * N);
        const float* rr = RESID ? (A + (size_t)row * K) : nullptr; // K==N here
#pragma unroll
        for (int j = 0; j < 4; j++) {
            int col = colBase + tx + 16 * j;
            float v = acc[i][j] + bias[col];
            if (RELU)  v = fmaxf(v, 0.f);
            if (RESID) v += rr[col];
            cr[col] = v;
        }
    }
}

// ---------------- VQ: fp32-sequential GEMM + rounding-faithful argmin --------
// Reference computes d_k = fl32( fl32(zz + ee_k) − fl32(2*ge_k) ).
//  * ee_k <= 3.8e-6 < ulp(zz)/2  →  fl32(zz+ee)=zz always (annihilated).
//  * representables near zz are zz + j*ulp(zz), so
//      fl32(zz − t) = zz − ulp * rint(t/ulp),  t = 2*ge  (grid phase is
//      independent of zz's mantissa!).
//  Winner = first k maximizing r_k = ulp * rint(t_k/ulp)  (half-even rint).
//  acc is accumulated with sequential ascending-k fp32 FMAs to mirror the
//  reference cublas sgemm rounding, so t matches the reference bit-for-bit
//  up to the last-ulp noise of z itself.
__global__ __launch_bounds__(256)
void vq_argmin_kernel(const float* __restrict__ Z, const float* __restrict__ E,
                      const double* __restrict__ ZZ,
                      unsigned long long* __restrict__ amin)
{
    __shared__ float As[16][128];
    __shared__ float Bs[16][64];
    const int tid = threadIdx.x;
    const int tx = tid & 15, ty = tid >> 4;
    const int rowBase = blockIdx.y * 128;
    const int colBase = blockIdx.x * 64;

    float acc[8][4];
#pragma unroll
    for (int i = 0; i < 8; i++)
#pragma unroll
        for (int j = 0; j < 4; j++) acc[i][j] = 0.f;

    for (int k0 = 0; k0 < DLAT; k0 += 16) {
#pragma unroll
        for (int s = 0; s < 2; s++) {
            int f = tid + s * 256;
            int r = f >> 2, c4 = f & 3;
            float4 v = *(reinterpret_cast<const float4*>(
                           Z + (size_t)(rowBase + r) * DLAT + k0) + c4);
            As[c4 * 4 + 0][r] = v.x; As[c4 * 4 + 1][r] = v.y;
            As[c4 * 4 + 2][r] = v.z; As[c4 * 4 + 3][r] = v.w;
        }
        {
            int n = tid >> 2, d4 = tid & 3;  // E rows are the "N" dim (NT gemm)
            float4 v = *(reinterpret_cast<const float4*>(
                           E + (size_t)(colBase + n) * DLAT + k0) + d4);
            Bs[d4 * 4 + 0][n] = v.x; Bs[d4 * 4 + 1][n] = v.y;
            Bs[d4 * 4 + 2][n] = v.z; Bs[d4 * 4 + 3][n] = v.w;
        }
        __syncthreads();
#pragma unroll
        for (int kk = 0; kk < 16; kk++) {
            float ra[8], rb[4];
#pragma unroll
            for (int i = 0; i < 8; i++) ra[i] = As[kk][ty + 16 * i];
#pragma unroll
            for (int j = 0; j < 4; j++) rb[j] = Bs[kk][tx + 16 * j];
#pragma unroll
            for (int i = 0; i < 8; i++)
#pragma unroll
                for (int j = 0; j < 4; j++)
                    acc[i][j] = fmaf(ra[i], rb[j], acc[i][j]);
        }
        __syncthreads();
    }

#pragma unroll
    for (int i = 0; i < 8; i++) {
        int row = rowBase + ty + 16 * i;
        double zz = ZZ[row];
        unsigned long long best = ~0ull;
#pragma unroll
        for (int j = 0; j < 4; j++) {
            int col = colBase + tx + 16 * j;
            // t = fl32(2 * fl32(ge))  (doubling is exact)
            double t = 2.0 * (double)acc[i][j];
            double d = zz - t;                        // > 0 always (zz ~ 300)
            long long db = __double_as_longlong(d);
            int ebias = (int)((db >> 52) & 0x7ff);    // biased exponent of d
            double cell = __longlong_as_double((long long)(ebias - 23) << 52);
            double r = cell * rint(t / cell);         // exact: cell = 2^e, |m|<2^12
            float rf = (float)r;                      // exact
            unsigned u = __float_as_uint(rf);
            u = (u & 0x80000000u) ? ~u : (u | 0x80000000u);  // order-preserving
            unsigned long long key =
                ((unsigned long long)(~u) << 32) | (unsigned)col; // max r, min col
            if (key < best) best = key;
        }
#pragma unroll
        for (int o = 8; o; o >>= 1) {
            unsigned long long oth = __shfl_down_sync(0xffffffffu, best, o, 16);
            if (oth < best) best = oth;
        }
        if (tx == 0) atomicMin(&amin[row], best);
    }
}

// ---------------- VQ finalize: gather q, straight-through zq, loss ----------
__global__ void vq_finalize_kernel(const float* __restrict__ Z,
                                   const float* __restrict__ E,
                                   const unsigned long long* __restrict__ amin,
                                   float* __restrict__ zq,
                                   float* __restrict__ loss)
{
    int row  = blockIdx.x * 8 + (threadIdx.x >> 5);
    int lane = threadIdx.x & 31;
    int idx  = (int)(amin[row] & 0xffffffffull);
    const float4* zp = reinterpret_cast<const float4*>(Z) + (size_t)row * (DLAT / 4);
    const float4* ep = reinterpret_cast<const float4*>(E) + (size_t)idx * (DLAT / 4);
    float4* qp = reinterpret_cast<float4*>(zq) + (size_t)row * (DLAT / 4);
    float s = 0.f;
#pragma unroll
    for (int t = 0; t < 2; t++) {
        float4 z = zp[lane + 32 * t], e = ep[lane + 32 * t];
        float dx = e.x - z.x, dy = e.y - z.y, dz = e.z - z.z, dw = e.w - z.w;
        float4 o;                 // zq = z + (q - z), same op order as reference
        o.x = z.x + dx; o.y = z.y + dy; o.z = z.z + dz; o.w = z.w + dw;
        qp[lane + 32 * t] = o;
        s += dx * dx + dy * dy + dz * dz + dw * dw;
    }
#pragma unroll
    for (int o = 16; o; o >>= 1) s += __shfl_down_sync(0xffffffffu, s, o);
    if (lane == 0) loss[row] = s + BETA_F * s;   // emb + beta*com, com==emb in fp
}

// ---------------- launcher ----------------
extern "C" void kernel_launch(void* const* d_in, const int* in_sizes, int n_in,
                              void* d_out, int out_size)
{
    const float* x_a      = (const float*)d_in[0];
    const float* x_b      = (const float*)d_in[1];
    const float* enc_a_w  = (const float*)d_in[2];
    const float* enc_a_b  = (const float*)d_in[3];
    const float* enc_a_rw = (const float*)d_in[4];
    const float* enc_a_rb = (const float*)d_in[5];
    const float* enc_b_w  = (const float*)d_in[6];
    const float* enc_b_b  = (const float*)d_in[7];
    const float* enc_b_rw = (const float*)d_in[8];
    const float* enc_b_rb = (const float*)d_in[9];
    const float* dec_a_rw = (const float*)d_in[10];
    const float* dec_a_rb = (const float*)d_in[11];
    const float* dec_a_w  = (const float*)d_in[12];
    const float* dec_a_b  = (const float*)d_in[13];
    const float* dec_b_rw = (const float*)d_in[14];
    const float* dec_b_rb = (const float*)d_in[15];
    const float* dec_b_w  = (const float*)d_in[16];
    const float* dec_b_b  = (const float*)d_in[17];
    const float* codebook = (const float*)d_in[18];

    float *ze_a0, *ze_a1, *ze_b0, *ze_b1, *h0, *h1;
    double *zz_a, *zz_b;
    unsigned long long *amin_a, *amin_b;
    cudaGetSymbolAddress((void**)&ze_a0, g_ze_a0);
    cudaGetSymbolAddress((void**)&ze_a1, g_ze_a1);
    cudaGetSymbolAddress((void**)&ze_b0, g_ze_b0);
    cudaGetSymbolAddress((void**)&ze_b1, g_ze_b1);
    cudaGetSymbolAddress((void**)&h0, g_h0);
    cudaGetSymbolAddress((void**)&h1, g_h1);
    cudaGetSymbolAddress((void**)&zz_a, g_zz_a);
    cudaGetSymbolAddress((void**)&zz_b, g_zz_b);
    cudaGetSymbolAddress((void**)&amin_a, g_amin_a);
    cudaGetSymbolAddress((void**)&amin_b, g_amin_b);

    float* out = (float*)d_out;
    const size_t OFF_ZA = 0;
    const size_t OFF_ZB = (size_t)BATCH * DLAT;
    const size_t OFF_LA = 2 * OFF_ZB;
    const size_t OFF_LB = OFF_LA + BATCH;
    const size_t OFF_RA = OFF_LB + BATCH;
    const size_t OFF_RB = OFF_RA + (size_t)BATCH * DINA;
    const size_t OFF_XA = OFF_RB + (size_t)BATCH * DINB;
    const size_t OFF_XB = OFF_XA + (size_t)BATCH * DINA;

    init_amin_kernel<<<(BATCH + 255) / 256, 256>>>();

    dim3 gLat(DLAT / 64, BATCH / 128);         // [8192,256] outputs
    dim3 gLat2(DLAT / 64, 2 * BATCH / 128);    // [16384,256] outputs

    // encoder A
    gemm_kernel<true, false><<<gLat, 256>>>(x_a, enc_a_w, enc_a_b,
        ze_a0, ze_a0, BATCH, BATCH, DLAT, DINA);
    gemm_kernel<true, true><<<gLat, 256>>>(ze_a0, enc_a_rw, enc_a_rb,
        ze_a1, ze_a1, BATCH, BATCH, DLAT, DLAT);
    gemm_kernel<true, true><<<gLat, 256>>>(ze_a1, enc_a_rw + DLAT * DLAT, enc_a_rb + DLAT,
        ze_a0, ze_a0, BATCH, BATCH, DLAT, DLAT);

    // encoder B
    gemm_kernel<true, false><<<gLat, 256>>>(x_b, enc_b_w, enc_b_b,
        ze_b0, ze_b0, BATCH, BATCH, DLAT, DINB);
    gemm_kernel<true, true><<<gLat, 256>>>(ze_b0, enc_b_rw, enc_b_rb,
        ze_b1, ze_b1, BATCH, BATCH, DLAT, DLAT);
    gemm_kernel<true, true><<<gLat, 256>>>(ze_b1, enc_b_rw + DLAT * DLAT, enc_b_rb + DLAT,
        ze_b0, ze_b0, BATCH, BATCH, DLAT, DLAT);

    // row norms (fp64; binade anchor for the rounding grid)
    zz_kernel<<<BATCH / 8, 256>>>(ze_a0, zz_a);
    zz_kernel<<<BATCH / 8, 256>>>(ze_b0, zz_b);

    // VQ argmin with reference-faithful fp32 rounding emulation
    dim3 gVQ(NCODE / 64, BATCH / 128);
    vq_argmin_kernel<<<gVQ, 256>>>(ze_a0, codebook, zz_a, amin_a);
    vq_argmin_kernel<<<gVQ, 256>>>(ze_b0, codebook, zz_b, amin_b);

    vq_finalize_kernel<<<BATCH / 8, 256>>>(ze_a0, codebook, amin_a,
                                           out + OFF_ZA, out + OFF_LA);
    vq_finalize_kernel<<<BATCH / 8, 256>>>(ze_b0, codebook, amin_b,
                                           out + OFF_ZB, out + OFF_LB);

    // decoders, batched over [zq_a; zq_b] (contiguous in d_out)
    const float* Zq = out;

    gemm_kernel<true, true><<<gLat2, 256>>>(Zq, dec_a_rw, dec_a_rb,
        h1, h1, 2 * BATCH, 2 * BATCH, DLAT, DLAT);
    gemm_kernel<true, true><<<gLat2, 256>>>(h1, dec_a_rw + DLAT * DLAT, dec_a_rb + DLAT,
        h0, h0, 2 * BATCH, 2 * BATCH, DLAT, DLAT);
    gemm_kernel<false, false><<<dim3(DINA / 64, 2 * BATCH / 128), 256>>>(
        h0, dec_a_w, dec_a_b,
        out + OFF_RA, out + OFF_XA, BATCH, 2 * BATCH, DINA, DLAT);

    gemm_kernel<true, true><<<gLat2, 256>>>(Zq, dec_b_rw, dec_b_rb,
        h1, h1, 2 * BATCH, 2 * BATCH, DLAT, DLAT);
    gemm_kernel<true, true><<<gLat2, 256>>>(h1, dec_b_rw + DLAT * DLAT, dec_b_rb + DLAT,
        h0, h0, 2 * BATCH, 2 * BATCH, DLAT, DLAT);
    gemm_kernel<false, false><<<dim3(DINB / 64, 2 * BATCH / 128), 256>>>(
        h0, dec_b_w, dec_b_b,
        out + OFF_XB, out + OFF_RB, BATCH, 2 * BATCH, DINB, DLAT);
}